// round 15
// baseline (speedup 1.0000x reference)
#include <cuda_runtime.h>
#include <math.h>

#define HID  64
#define HID2 (HID/2)
#define PTS  64      // points per CTA (a phys point AND a data point per pt)
#define BDP  512     // 8 threads per point; each owns 8 output neurons
#define NW   (BDP/32)

__device__ double g_sums[2];   // [0] = sum (pred-y)^2, [1] = sum residual^2

__global__ void k_zero() { g_sums[0] = 0.0; g_sums[1] = 0.0; }

// Fast, branch-free tanh (abs err ~1e-6).
__device__ __forceinline__ float my_tanhf(float z) {
    float zc = fminf(fmaxf(z, -15.f), 15.f);
    float e  = __expf(2.f * zc);
    return 1.f - __fdividef(2.f, e + 1.f);
}

// ---- packed f32x2 helpers ---------------------------------------------------
__device__ __forceinline__ void ffma2(unsigned long long& a,
                                      unsigned long long x, unsigned long long y) {
    asm("fma.rn.f32x2 %0, %1, %2, %0;" : "+l"(a) : "l"(x), "l"(y));
}
__device__ __forceinline__ float2 unpk(unsigned long long a) {
    float2 f;
    asm("mov.b64 {%0, %1}, %2;" : "=f"(f.x), "=f"(f.y) : "l"(a));
    return f;
}
// Horizontal sum of an i-split accumulator.
__device__ __forceinline__ float hsum(unsigned long long a) {
    float2 f = unpk(a);
    return f.x + f.y;
}

// i-paired matvec: zA[m]/zB[m] accumulate (even-i, odd-i) partial dot products
// for j = jbase+m over channels A and B of one interleaved float4 buffer.
// stP layout: [HID2][PTS] of (A_2i', A_2i'+1, B_2i', B_2i'+1).
// wp  layout: [HID2][HID/2] ulonglong2, each = pairs for j, j+1:
//             ((W[2i'][j],W[2i'+1][j]), (W[2i'][j+1],W[2i'+1][j+1])).
__device__ __forceinline__ void matvec_ip(const ulonglong2* __restrict__ stP,
                                          const ulonglong2* __restrict__ wp,
                                          unsigned long long* zA,
                                          unsigned long long* zB,
                                          int pt, int jbase) {
    #pragma unroll 4
    for (int ip = 0; ip < HID2; ip++) {
        ulonglong2 sv = stP[ip * PTS + pt];        // 1 LDS.128, zero MOVs
        const ulonglong2* wr = wp + ip * (HID / 2) + (jbase >> 1);
        #pragma unroll
        for (int k = 0; k < 4; k++) {
            ulonglong2 w = wr[k];                  // LDS.128 broadcast: j-pairs
            ffma2(zA[2 * k],     sv.x, w.x);
            ffma2(zA[2 * k + 1], sv.x, w.y);
            ffma2(zB[2 * k],     sv.y, w.x);
            ffma2(zB[2 * k + 1], sv.y, w.y);
        }
    }
}

// ============================================================================
// Fully fused kernel. Interleaved i-paired channel buffers in SMEM:
//   P0 = (h, ut)   P1 = (ux, uy)   P2 = (L, hd)
// 8 threads per point (oct = tid>>6 owns j in [8*oct, 8*oct+8)).
// f32x2 packs the i dimension (even/odd partial sums) -> no dup MOVs.
// 112 KB SMEM/CTA -> 2 CTAs/SM -> 8 warps/SMSP.
// ============================================================================
__global__ __launch_bounds__(BDP, 2) void k_fused(
    const float* __restrict__ xd,       // x_data
    const float* __restrict__ yd,       // y_data
    const float* __restrict__ xp,       // x_phys
    const float* __restrict__ W0, const float* __restrict__ b0,
    const float* __restrict__ W1, const float* __restrict__ b1,
    const float* __restrict__ W2, const float* __restrict__ b2,
    const float* __restrict__ W3, const float* __restrict__ b3,
    const float* __restrict__ W4, const float* __restrict__ b4,
    const float* __restrict__ log_alpha,
    int n)
{
    extern __shared__ float sh[];
    float4* P0 = (float4*)sh;                     // [HID2][PTS]
    float4* P1 = P0 + HID2 * PTS;
    float4* P2 = P1 + HID2 * PTS;
    float2* wp = (float2*)(sh + 6 * HID * PTS / 2 * 2);  // after 96 KB of state
    float*  wscr = (float*)wp;                    // scratch alias (post-barrier)
    const int tid   = threadIdx.x;
    const int pt    = tid & (PTS - 1);
    const int oct   = tid >> 6;                   // 0..7
    const int jbase = oct << 3;                   // 0,8,...,56
    const int p     = blockIdx.x * PTS + pt;
    const bool active = p < n;

    float px0 = 0.f, px1 = 0.f, px2 = 0.f;        // phys point
    float dx0 = 0.f, dx1 = 0.f, dx2 = 0.f;        // data point
    if (active) {
        px0 = xp[3 * p]; px1 = xp[3 * p + 1]; px2 = xp[3 * p + 2];
        dx0 = xd[3 * p]; dx1 = xd[3 * p + 1]; dx2 = xd[3 * p + 2];
    }

    // ---- layer 0: 3 -> 64, own 8 neurons (4 j-pairs), all channels ----
    #pragma unroll
    for (int m = 0; m < 4; m++) {
        float t_[2], ut_[2], ux_[2], uy_[2], L_[2], hd_[2];
        #pragma unroll
        for (int hh = 0; hh < 2; hh++) {
            int j = jbase + 2 * m + hh;
            float wx = __ldg(W0 + j);
            float wy = __ldg(W0 + HID + j);
            float wt = __ldg(W0 + 2 * HID + j);
            float bj = __ldg(b0 + j);
            float zh = bj + px0 * wx + px1 * wy + px2 * wt;
            float zd = bj + dx0 * wx + dx1 * wy + dx2 * wt;
            float t = my_tanhf(zh);
            float s = 1.f - t * t;
            t_[hh]  = t;
            ut_[hh] = s * wt;
            ux_[hh] = s * wx;
            uy_[hh] = s * wy;
            L_[hh]  = -2.f * t * s * (wx * wx + wy * wy);
            hd_[hh] = my_tanhf(zd);
        }
        int ip = (jbase >> 1) + m;                // i' row for next layer
        P0[ip * PTS + pt] = make_float4(t_[0],  t_[1],  ut_[0], ut_[1]);
        P1[ip * PTS + pt] = make_float4(ux_[0], ux_[1], uy_[0], uy_[1]);
        P2[ip * PTS + pt] = make_float4(L_[0],  L_[1],  hd_[0], hd_[1]);
    }

    float q_r[8];    // zx^2+zy^2 for own j (set in epi1, used in epi2)

    // ---- hidden layers 1..3 ----
    #pragma unroll 1
    for (int l = 0; l < 3; l++) {
        const float* W  = (l == 0) ? W1 : (l == 1) ? W2 : W3;
        const float* bb = (l == 0) ? b1 : (l == 1) ? b2 : b3;

        __syncthreads();   // prev-layer epi writes visible; wp reads retired
        // Stage weights as i-transpose-pairs: wp[i'][j] = (W[2i'][j], W[2i'+1][j])
        #pragma unroll
        for (int r = 0; r < (HID2 * HID) / BDP; r++) {       // 4 pairs/thread
            int idx = r * BDP + tid;
            int ip = idx >> 6, j = idx & (HID - 1);
            wp[idx] = make_float2(__ldg(W + (2 * ip) * HID + j),
                                  __ldg(W + (2 * ip + 1) * HID + j));
        }
        __syncthreads();

        unsigned long long zA[8], zB[8];

        // --- pass0: (h, ut) ---
        #pragma unroll
        for (int m = 0; m < 8; m++) { zA[m] = 0ull; zB[m] = 0ull; }
        matvec_ip((const ulonglong2*)P0, (const ulonglong2*)wp, zA, zB, pt, jbase);
        __syncthreads();                    // all reads of P0 done
        #pragma unroll
        for (int m = 0; m < 4; m++) {
            float2 bv = __ldg((const float2*)bb + (jbase >> 1) + m);
            float t0 = my_tanhf(hsum(zA[2 * m])     + bv.x);
            float t1 = my_tanhf(hsum(zA[2 * m + 1]) + bv.y);
            float s0 = 1.f - t0 * t0;
            float s1 = 1.f - t1 * t1;
            int ip = (jbase >> 1) + m;
            P0[ip * PTS + pt] = make_float4(t0, t1,
                                            s0 * hsum(zB[2 * m]),
                                            s1 * hsum(zB[2 * m + 1]));
        }

        // --- pass1: (ux, uy). Epi: q_r = zx^2+zy^2; write (s*zx, s*zy) ---
        #pragma unroll
        for (int m = 0; m < 8; m++) { zA[m] = 0ull; zB[m] = 0ull; }
        matvec_ip((const ulonglong2*)P1, (const ulonglong2*)wp, zA, zB, pt, jbase);
        __syncthreads();                    // all reads of P1 done
        #pragma unroll
        for (int m = 0; m < 4; m++) {
            int ip = (jbase >> 1) + m;
            float4 p0v = P0[ip * PTS + pt];         // self-written in epi0
            float zx0 = hsum(zA[2 * m]),     zx1 = hsum(zA[2 * m + 1]);
            float zy0 = hsum(zB[2 * m]),     zy1 = hsum(zB[2 * m + 1]);
            float s0 = 1.f - p0v.x * p0v.x;
            float s1 = 1.f - p0v.y * p0v.y;
            P1[ip * PTS + pt] = make_float4(s0 * zx0, s1 * zx1, s0 * zy0, s1 * zy1);
            q_r[2 * m]     = zx0 * zx0 + zy0 * zy0;
            q_r[2 * m + 1] = zx1 * zx1 + zy1 * zy1;
        }

        // --- pass2: (L, hd). Epi: L=s*zL-2*t*s*q; hd=tanh(zd+b) ---
        #pragma unroll
        for (int m = 0; m < 8; m++) { zA[m] = 0ull; zB[m] = 0ull; }
        matvec_ip((const ulonglong2*)P2, (const ulonglong2*)wp, zA, zB, pt, jbase);
        __syncthreads();                    // all reads of P2 done
        #pragma unroll
        for (int m = 0; m < 4; m++) {
            float2 bv = __ldg((const float2*)bb + (jbase >> 1) + m);
            int ip = (jbase >> 1) + m;
            float4 p0v = P0[ip * PTS + pt];
            float zl0 = hsum(zA[2 * m]),     zl1 = hsum(zA[2 * m + 1]);
            float zd0 = hsum(zB[2 * m]) + bv.x;
            float zd1 = hsum(zB[2 * m + 1]) + bv.y;
            float t0 = p0v.x, t1 = p0v.y;
            float s0 = 1.f - t0 * t0;
            float s1 = 1.f - t1 * t1;
            P2[ip * PTS + pt] = make_float4(
                s0 * zl0 - 2.f * t0 * s0 * q_r[2 * m],
                s1 * zl1 - 2.f * t1 * s1 * q_r[2 * m + 1],
                my_tanhf(zd0), my_tanhf(zd1));
        }
    }

    // ---- output layer: partials over own 8 neurons (all self-written) ----
    float at = 0.f, aL = 0.f, ad = 0.f;
    #pragma unroll
    for (int m = 0; m < 4; m++) {
        int ip = (jbase >> 1) + m;
        float2 w4 = __ldg((const float2*)W4 + (jbase >> 1) + m);
        float4 v0 = P0[ip * PTS + pt];
        float4 v2 = P2[ip * PTS + pt];
        at += v0.z * w4.x + v0.w * w4.y;
        aL += v2.x * w4.x + v2.y * w4.y;
        ad += v2.z * w4.x + v2.w * w4.y;
    }
    float alpha = expf(__ldg(log_alpha));
    float rp = at - alpha * aL;             // partial residual (linear in partials)

    // wp/wscr free (post-pass2 barrier passed): combine the 8 octs per point
    wscr[oct * PTS + pt]            = rp;
    wscr[8 * PTS + oct * PTS + pt]  = ad;
    __syncthreads();

    double lr = 0.0, ld = 0.0;
    if (oct == 0 && active) {
        float r = rp, ah = ad;
        #pragma unroll
        for (int o = 1; o < 8; o++) {
            r  += wscr[o * PTS + pt];
            ah += wscr[8 * PTS + o * PTS + pt];
        }
        lr = (double)r * (double)r;
        ah += __ldg(b4);
        float d = ah - yd[p];
        ld = (double)d * (double)d;
    }

    // block reductions -> atomics (both sums)
    #pragma unroll
    for (int off = 16; off; off >>= 1) {
        lr += __shfl_down_sync(0xffffffffu, lr, off);
        ld += __shfl_down_sync(0xffffffffu, ld, off);
    }
    __syncthreads();
    double* red = (double*)sh;              // 2*NW doubles
    int lane = tid & 31, wid = tid >> 5;
    if (lane == 0) { red[wid] = lr; red[NW + wid] = ld; }
    __syncthreads();
    if (tid == 0) {
        double sr = 0.0, sd = 0.0;
        #pragma unroll
        for (int w = 0; w < NW; w++) { sr += red[w]; sd += red[NW + w]; }
        atomicAdd(&g_sums[1], sr);
        atomicAdd(&g_sums[0], sd);
    }
}

__global__ void k_final(const float* __restrict__ log_lambda,
                        const float* __restrict__ log_alpha,
                        float* __restrict__ out, int n)
{
    float data_loss = (float)(g_sums[0] / (double)n);
    float pde_loss  = (float)(g_sums[1] / (double)n);
    float alpha = expf(log_alpha[0]);
    float lam   = expf(log_lambda[0]);
    out[0] = data_loss + lam * pde_loss;
    out[1] = data_loss;
    out[2] = pde_loss;
    out[3] = alpha;
    out[4] = lam;
}

extern "C" void kernel_launch(void* const* d_in, const int* in_sizes, int n_in,
                              void* d_out, int out_size)
{
    const float* x_data     = (const float*)d_in[0];
    const float* y_data     = (const float*)d_in[1];
    const float* x_phys     = (const float*)d_in[2];
    const float* W0 = (const float*)d_in[3];  const float* b0 = (const float*)d_in[4];
    const float* W1 = (const float*)d_in[5];  const float* b1 = (const float*)d_in[6];
    const float* W2 = (const float*)d_in[7];  const float* b2 = (const float*)d_in[8];
    const float* W3 = (const float*)d_in[9];  const float* b3 = (const float*)d_in[10];
    const float* W4 = (const float*)d_in[11]; const float* b4 = (const float*)d_in[12];
    const float* log_lambda = (const float*)d_in[13];
    const float* log_alpha  = (const float*)d_in[14];
    float* out = (float*)d_out;

    int n = in_sizes[0] / 3;

    // 3 i-paired state buffers (96 KB) + transpose-pair weights (16 KB) = 112 KB
    const int SH = (6 * HID * PTS + HID * HID) * (int)sizeof(float);
    cudaFuncSetAttribute(k_fused, cudaFuncAttributeMaxDynamicSharedMemorySize, SH);

    int grid = (n + PTS - 1) / PTS;

    k_zero<<<1, 1>>>();
    k_fused<<<grid, BDP, SH>>>(x_data, y_data, x_phys, W0, b0, W1, b1, W2, b2,
                               W3, b3, W4, b4, log_alpha, n);
    k_final<<<1, 1>>>(log_lambda, log_alpha, out, n);
}

// round 16
// speedup vs baseline: 1.2280x; 1.2280x over previous
#include <cuda_runtime.h>
#include <math.h>

#define HID 64
#define PTS 64       // points per CTA (a phys point AND a data point per pt)
#define BDP 512      // 8 threads per point; each owns 8 output neurons
#define NW  (BDP/32)

__device__ double g_sums[2];   // [0] = sum (pred-y)^2, [1] = sum residual^2

__global__ void k_zero() { g_sums[0] = 0.0; g_sums[1] = 0.0; }

// Fast, branch-free tanh (abs err ~1e-6).
__device__ __forceinline__ float my_tanhf(float z) {
    float zc = fminf(fmaxf(z, -15.f), 15.f);
    float e  = __expf(2.f * zc);
    return 1.f - __fdividef(2.f, e + 1.f);
}

// Group barrier: syncs the 8 warps (256 threads) of one point-group.
// Group 0 = even warps (pts 0-31), group 1 = odd warps (pts 32-63).
__device__ __forceinline__ void group_bar(int g) {
    asm volatile("bar.sync %0, 256;" :: "r"(1 + g) : "memory");
}

// ---- packed f32x2 helpers (FFMA2 path, sm_100+) ----------------------------
__device__ __forceinline__ unsigned long long dup2(float v) {
    unsigned long long r;
    asm("mov.b64 %0, {%1, %1};" : "=l"(r) : "f"(v));
    return r;
}
__device__ __forceinline__ unsigned long long pack2(float lo, float hi) {
    unsigned long long r;
    asm("mov.b64 %0, {%1, %2};" : "=l"(r) : "f"(lo), "f"(hi));
    return r;
}
__device__ __forceinline__ void ffma2(unsigned long long& a,
                                      unsigned long long x, unsigned long long y) {
    asm("fma.rn.f32x2 %0, %1, %2, %0;" : "+l"(a) : "l"(x), "l"(y));
}
__device__ __forceinline__ float2 unpk(unsigned long long a) {
    float2 f;
    asm("mov.b64 {%0, %1}, %2;" : "=f"(f.x), "=f"(f.y) : "l"(a));
    return f;
}

// Paired matvec over the 8 owned j (4 f32x2 pairs per channel).
// State pair (chA,chB) comes from ONE interleaved float2 buffer: 1 LDS.64/i.
__device__ __forceinline__ void matvec2p(const float2* __restrict__ stP,
                                         const float* __restrict__ wsh,
                                         unsigned long long* zA,
                                         unsigned long long* zB,
                                         int pt, int jbase) {
    #pragma unroll 8
    for (int i = 0; i < HID; i++) {
        float2 v = stP[i * PTS + pt];            // (chA, chB) for this i, point
        unsigned long long vA = dup2(v.x);
        unsigned long long vB = dup2(v.y);
        const ulonglong2* wr = (const ulonglong2*)(wsh + i * HID + jbase);
        #pragma unroll
        for (int k = 0; k < 2; k++) {
            ulonglong2 w = wr[k];                // LDS.128, warp-uniform broadcast
            ffma2(zA[2 * k],     vA, w.x);
            ffma2(zA[2 * k + 1], vA, w.y);
            ffma2(zB[2 * k],     vB, w.x);
            ffma2(zB[2 * k + 1], vB, w.y);
        }
    }
}

// ============================================================================
// Fully fused kernel. Interleaved channel pairs in SMEM:
//   P0 = (h, ut)   P1 = (ux, uy)   P2 = (L, hd)
// 8 threads per point (oct = tid>>6 owns j in [8*oct, 8*oct+8)).
// Per layer: pass0=P0, pass1=P1, pass2=P2; q and t live in registers
// (thread-local across passes by consistent j-ownership).
// Pass barriers are GROUP barriers (even/odd warps = pts 0-31 / 32-63);
// full barriers only around the shared weight buffer.
// 112 KB SMEM/CTA -> 2 CTAs/SM -> 8 warps/SMSP.
// ============================================================================
__global__ __launch_bounds__(BDP, 2) void k_fused(
    const float* __restrict__ xd,       // x_data
    const float* __restrict__ yd,       // y_data
    const float* __restrict__ xp,       // x_phys
    const float* __restrict__ W0, const float* __restrict__ b0,
    const float* __restrict__ W1, const float* __restrict__ b1,
    const float* __restrict__ W2, const float* __restrict__ b2,
    const float* __restrict__ W3, const float* __restrict__ b3,
    const float* __restrict__ W4, const float* __restrict__ b4,
    const float* __restrict__ log_alpha,
    int n)
{
    extern __shared__ float sh[];
    float2* P0 = (float2*)sh;                    // [HID][PTS] pairs
    float2* P1 = P0 + HID * PTS;
    float2* P2 = P1 + HID * PTS;
    float*  wsh = sh + 6 * HID * PTS;            // 64x64 staged weights / scratch
    const int tid   = threadIdx.x;
    const int pt    = tid & (PTS - 1);
    const int oct   = tid >> 6;                  // 0..7
    const int jbase = oct << 3;                  // 0,8,...,56
    const int grp   = (pt >> 5) & 1;             // 0: even warps, 1: odd warps
    const int p     = blockIdx.x * PTS + pt;
    const bool active = p < n;

    float px0 = 0.f, px1 = 0.f, px2 = 0.f;       // phys point
    float dx0 = 0.f, dx1 = 0.f, dx2 = 0.f;       // data point
    if (active) {
        px0 = xp[3 * p]; px1 = xp[3 * p + 1]; px2 = xp[3 * p + 2];
        dx0 = xd[3 * p]; dx1 = xd[3 * p + 1]; dx2 = xd[3 * p + 2];
    }

    // ---- layer 0: 3 -> 64, own 8 neurons, all channels ----
    #pragma unroll 4
    for (int jj = 0; jj < 8; jj++) {
        int j = jbase + jj;
        float wx = __ldg(W0 + j);
        float wy = __ldg(W0 + HID + j);
        float wt = __ldg(W0 + 2 * HID + j);
        float bj = __ldg(b0 + j);
        float zh = bj + px0 * wx + px1 * wy + px2 * wt;
        float zd = bj + dx0 * wx + dx1 * wy + dx2 * wt;
        float t = my_tanhf(zh);
        float s = 1.f - t * t;
        P0[j * PTS + pt] = make_float2(t, s * wt);
        P1[j * PTS + pt] = make_float2(s * wx, s * wy);
        P2[j * PTS + pt] = make_float2(-2.f * t * s * (wx * wx + wy * wy),
                                       my_tanhf(zd));
    }

    float t_r[8];    // tanh(z) for own j, current layer (set in epi0)
    float q_r[8];    // zx^2+zy^2 for own j (set in epi1, used in epi2)

    // ---- hidden layers 1..3 ----
    #pragma unroll 1
    for (int l = 0; l < 3; l++) {
        const float* W  = (l == 0) ? W1 : (l == 1) ? W2 : W3;
        const float* bb = (l == 0) ? b1 : (l == 1) ? b2 : b3;

        __syncthreads();   // FULL: prev-layer epi writes visible; wsh reads retired
        {
            const float4* src = (const float4*)W;
            float4*       dst = (float4*)wsh;
            #pragma unroll
            for (int k = 0; k < (HID * HID / 4) / BDP; k++)   // 2 float4/thread
                dst[k * BDP + tid] = src[k * BDP + tid];
        }
        __syncthreads();   // FULL: weights staged for both groups

        unsigned long long zA[4], zB[4];

        // --- pass0: (h, ut). zA = b + h@W ; zB = ut@W ---
        #pragma unroll
        for (int m = 0; m < 4; m++) {
            float2 bv = __ldg((const float2*)bb + (jbase >> 1) + m);
            zA[m] = pack2(bv.x, bv.y);
            zB[m] = 0ull;
        }
        matvec2p(P0, wsh, zA, zB, pt, jbase);
        group_bar(grp);                     // group's reads of P0 done
        #pragma unroll
        for (int m = 0; m < 4; m++) {
            float2 zh = unpk(zA[m]);
            float2 zt = unpk(zB[m]);
            #pragma unroll
            for (int hh = 0; hh < 2; hh++) {
                int j = jbase + 2 * m + hh;
                float t = my_tanhf(hh ? zh.y : zh.x);
                float s = 1.f - t * t;
                t_r[2 * m + hh] = t;
                P0[j * PTS + pt] = make_float2(t, s * (hh ? zt.y : zt.x));
            }
        }

        // --- pass1: (ux, uy). Epi: q_r = zx^2+zy^2; write (s*zx, s*zy) ---
        #pragma unroll
        for (int m = 0; m < 4; m++) { zA[m] = 0ull; zB[m] = 0ull; }
        matvec2p(P1, wsh, zA, zB, pt, jbase);
        group_bar(grp);                     // group's reads of P1 done
        #pragma unroll
        for (int m = 0; m < 4; m++) {
            float2 zx = unpk(zA[m]);
            float2 zy = unpk(zB[m]);
            #pragma unroll
            for (int hh = 0; hh < 2; hh++) {
                int j = jbase + 2 * m + hh;
                float zxv = hh ? zx.y : zx.x;
                float zyv = hh ? zy.y : zy.x;
                float t = t_r[2 * m + hh];
                float s = 1.f - t * t;
                P1[j * PTS + pt] = make_float2(s * zxv, s * zyv);
                q_r[2 * m + hh] = zxv * zxv + zyv * zyv;
            }
        }

        // --- pass2: (L, hd). Epi: L=s*zL-2*t*s*q; hd=tanh(zd+b) ---
        #pragma unroll
        for (int m = 0; m < 4; m++) {
            float2 bv = __ldg((const float2*)bb + (jbase >> 1) + m);
            zA[m] = 0ull;
            zB[m] = pack2(bv.x, bv.y);      // data channel carries the bias
        }
        matvec2p(P2, wsh, zA, zB, pt, jbase);
        group_bar(grp);                     // group's reads of P2 done
        #pragma unroll
        for (int m = 0; m < 4; m++) {
            float2 zl = unpk(zA[m]);
            float2 zd = unpk(zB[m]);
            #pragma unroll
            for (int hh = 0; hh < 2; hh++) {
                int j = jbase + 2 * m + hh;
                float zlv = hh ? zl.y : zl.x;
                float t = t_r[2 * m + hh];
                float s = 1.f - t * t;
                P2[j * PTS + pt] = make_float2(
                    s * zlv - 2.f * t * s * q_r[2 * m + hh],
                    my_tanhf(hh ? zd.y : zd.x));
            }
        }
    }

    // ---- output layer: partials over own 8 neurons (all self-written) ----
    float at = 0.f, aL = 0.f, ad = 0.f;
    #pragma unroll 4
    for (int jj = 0; jj < 8; jj++) {
        int j = jbase + jj;
        float w = __ldg(W4 + j);
        at += P0[j * PTS + pt].y * w;
        float2 v2 = P2[j * PTS + pt];
        aL += v2.x * w;
        ad += v2.y * w;
    }
    float alpha = expf(__ldg(log_alpha));
    float rp = at - alpha * aL;             // partial residual (linear in partials)

    // FULL barrier: wsh (scratch alias) reads by BOTH groups must be retired
    __syncthreads();
    wsh[oct * PTS + pt]            = rp;
    wsh[8 * PTS + oct * PTS + pt]  = ad;
    group_bar(grp);                         // combine is pt-local -> group is enough

    double lr = 0.0, ld = 0.0;
    if (oct == 0 && active) {
        float r = rp, ah = ad;
        #pragma unroll
        for (int o = 1; o < 8; o++) {
            r  += wsh[o * PTS + pt];
            ah += wsh[8 * PTS + o * PTS + pt];
        }
        lr = (double)r * (double)r;
        ah += __ldg(b4);
        float d = ah - yd[p];
        ld = (double)d * (double)d;
    }

    // block reductions -> atomics (both sums)
    #pragma unroll
    for (int off = 16; off; off >>= 1) {
        lr += __shfl_down_sync(0xffffffffu, lr, off);
        ld += __shfl_down_sync(0xffffffffu, ld, off);
    }
    __syncthreads();
    double* red = (double*)sh;              // 2*NW doubles
    int lane = tid & 31, wid = tid >> 5;
    if (lane == 0) { red[wid] = lr; red[NW + wid] = ld; }
    __syncthreads();
    if (tid == 0) {
        double sr = 0.0, sd = 0.0;
        #pragma unroll
        for (int w = 0; w < NW; w++) { sr += red[w]; sd += red[NW + w]; }
        atomicAdd(&g_sums[1], sr);
        atomicAdd(&g_sums[0], sd);
    }
}

__global__ void k_final(const float* __restrict__ log_lambda,
                        const float* __restrict__ log_alpha,
                        float* __restrict__ out, int n)
{
    float data_loss = (float)(g_sums[0] / (double)n);
    float pde_loss  = (float)(g_sums[1] / (double)n);
    float alpha = expf(log_alpha[0]);
    float lam   = expf(log_lambda[0]);
    out[0] = data_loss + lam * pde_loss;
    out[1] = data_loss;
    out[2] = pde_loss;
    out[3] = alpha;
    out[4] = lam;
}

extern "C" void kernel_launch(void* const* d_in, const int* in_sizes, int n_in,
                              void* d_out, int out_size)
{
    const float* x_data     = (const float*)d_in[0];
    const float* y_data     = (const float*)d_in[1];
    const float* x_phys     = (const float*)d_in[2];
    const float* W0 = (const float*)d_in[3];  const float* b0 = (const float*)d_in[4];
    const float* W1 = (const float*)d_in[5];  const float* b1 = (const float*)d_in[6];
    const float* W2 = (const float*)d_in[7];  const float* b2 = (const float*)d_in[8];
    const float* W3 = (const float*)d_in[9];  const float* b3 = (const float*)d_in[10];
    const float* W4 = (const float*)d_in[11]; const float* b4 = (const float*)d_in[12];
    const float* log_lambda = (const float*)d_in[13];
    const float* log_alpha  = (const float*)d_in[14];
    float* out = (float*)d_out;

    int n = in_sizes[0] / 3;

    // 3 pair-buffers (96 KB) + 64x64 weights (16 KB) = 112 KB -> 2 CTAs/SM
    const int SH = (6 * HID * PTS + HID * HID) * (int)sizeof(float);
    cudaFuncSetAttribute(k_fused, cudaFuncAttributeMaxDynamicSharedMemorySize, SH);

    int grid = (n + PTS - 1) / PTS;

    k_zero<<<1, 1>>>();
    k_fused<<<grid, BDP, SH>>>(x_data, y_data, x_phys, W0, b0, W1, b1, W2, b2,
                               W3, b3, W4, b4, log_alpha, n);
    k_final<<<1, 1>>>(log_lambda, log_alpha, out, n);
}

// round 17
// speedup vs baseline: 1.3034x; 1.0613x over previous
#include <cuda_runtime.h>
#include <math.h>

#define HID 64
#define PTS 64       // points per CTA (a phys point AND a data point per pt)
#define BDP 512      // 8 threads per point; each owns 8 output neurons
#define NW  (BDP/32)

__device__ double g_sums[2];   // [0] = sum (pred-y)^2, [1] = sum residual^2

__global__ void k_zero() { g_sums[0] = 0.0; g_sums[1] = 0.0; }

// Fast, branch-free tanh (abs err ~1e-6).
__device__ __forceinline__ float my_tanhf(float z) {
    float zc = fminf(fmaxf(z, -15.f), 15.f);
    float e  = __expf(2.f * zc);
    return 1.f - __fdividef(2.f, e + 1.f);
}

// Group barrier: syncs the 8 warps (256 threads) of one point-group.
// Group 0 = even warps (pts 0-31), group 1 = odd warps (pts 32-63).
__device__ __forceinline__ void group_bar(int g) {
    asm volatile("bar.sync %0, 256;" :: "r"(1 + g) : "memory");
}

// ---- packed f32x2 helpers (FFMA2 path, sm_100+) ----------------------------
__device__ __forceinline__ unsigned long long dup2(float v) {
    unsigned long long r;
    asm("mov.b64 %0, {%1, %1};" : "=l"(r) : "f"(v));
    return r;
}
__device__ __forceinline__ unsigned long long pack2(float lo, float hi) {
    unsigned long long r;
    asm("mov.b64 %0, {%1, %2};" : "=l"(r) : "f"(lo), "f"(hi));
    return r;
}
__device__ __forceinline__ void ffma2(unsigned long long& a,
                                      unsigned long long x, unsigned long long y) {
    asm("fma.rn.f32x2 %0, %1, %2, %0;" : "+l"(a) : "l"(x), "l"(y));
}
__device__ __forceinline__ float2 unpk(unsigned long long a) {
    float2 f;
    asm("mov.b64 {%0, %1}, %2;" : "=f"(f.x), "=f"(f.y) : "l"(a));
    return f;
}

// 2-channel matvec over the 8 owned j (4 f32x2 pairs per channel).
__device__ __forceinline__ void matvec2p(const float2* __restrict__ stP,
                                         const float* __restrict__ wsh,
                                         unsigned long long* zA,
                                         unsigned long long* zB,
                                         int pt, int jbase) {
    #pragma unroll 8
    for (int i = 0; i < HID; i++) {
        float2 v = stP[i * PTS + pt];            // (chA, chB) for this i, point
        unsigned long long vA = dup2(v.x);
        unsigned long long vB = dup2(v.y);
        const ulonglong2* wr = (const ulonglong2*)(wsh + i * HID + jbase);
        #pragma unroll
        for (int k = 0; k < 2; k++) {
            ulonglong2 w = wr[k];                // LDS.128, warp-uniform broadcast
            ffma2(zA[2 * k],     vA, w.x);
            ffma2(zA[2 * k + 1], vA, w.y);
            ffma2(zB[2 * k],     vB, w.x);
            ffma2(zB[2 * k + 1], vB, w.y);
        }
    }
}

// 4-channel matvec: channels (A,B) from stP, (C,D) from stQ.
// ONE weight broadcast pair serves all four channels.
__device__ __forceinline__ void matvec4p(const float2* __restrict__ stP,
                                         const float2* __restrict__ stQ,
                                         const float* __restrict__ wsh,
                                         unsigned long long* zA,
                                         unsigned long long* zB,
                                         unsigned long long* zC,
                                         unsigned long long* zD,
                                         int pt, int jbase) {
    #pragma unroll 4
    for (int i = 0; i < HID; i++) {
        float2 v1 = stP[i * PTS + pt];           // (ux, uy)
        float2 v2 = stQ[i * PTS + pt];           // (L, hd)
        unsigned long long vA = dup2(v1.x);
        unsigned long long vB = dup2(v1.y);
        unsigned long long vC = dup2(v2.x);
        unsigned long long vD = dup2(v2.y);
        const ulonglong2* wr = (const ulonglong2*)(wsh + i * HID + jbase);
        #pragma unroll
        for (int k = 0; k < 2; k++) {
            ulonglong2 w = wr[k];                // LDS.128, warp-uniform broadcast
            ffma2(zA[2 * k],     vA, w.x);
            ffma2(zA[2 * k + 1], vA, w.y);
            ffma2(zB[2 * k],     vB, w.x);
            ffma2(zB[2 * k + 1], vB, w.y);
            ffma2(zC[2 * k],     vC, w.x);
            ffma2(zC[2 * k + 1], vC, w.y);
            ffma2(zD[2 * k],     vD, w.x);
            ffma2(zD[2 * k + 1], vD, w.y);
        }
    }
}

// ============================================================================
// Fully fused kernel. Interleaved channel pairs in SMEM:
//   P0 = (h, ut)   P1 = (ux, uy)   P2 = (L, hd)
// 8 threads per point (oct = tid>>6 owns j in [8*oct, 8*oct+8)).
// Per layer: pass0 = (h,ut) matvec; pass12 = 4-channel (ux,uy,L,hd) matvec
// sharing one weight-load stream. q is epilogue-local; t carried in t_r.
// 2 group barriers per layer; full barriers only around the weight buffer.
// 112 KB SMEM/CTA -> 2 CTAs/SM -> 8 warps/SMSP.
// ============================================================================
__global__ __launch_bounds__(BDP, 2) void k_fused(
    const float* __restrict__ xd,       // x_data
    const float* __restrict__ yd,       // y_data
    const float* __restrict__ xp,       // x_phys
    const float* __restrict__ W0, const float* __restrict__ b0,
    const float* __restrict__ W1, const float* __restrict__ b1,
    const float* __restrict__ W2, const float* __restrict__ b2,
    const float* __restrict__ W3, const float* __restrict__ b3,
    const float* __restrict__ W4, const float* __restrict__ b4,
    const float* __restrict__ log_alpha,
    int n)
{
    extern __shared__ float sh[];
    float2* P0 = (float2*)sh;                    // [HID][PTS] pairs
    float2* P1 = P0 + HID * PTS;
    float2* P2 = P1 + HID * PTS;
    float*  wsh = sh + 6 * HID * PTS;            // 64x64 staged weights / scratch
    const int tid   = threadIdx.x;
    const int pt    = tid & (PTS - 1);
    const int oct   = tid >> 6;                  // 0..7
    const int jbase = oct << 3;                  // 0,8,...,56
    const int grp   = (pt >> 5) & 1;             // 0: even warps, 1: odd warps
    const int p     = blockIdx.x * PTS + pt;
    const bool active = p < n;

    float px0 = 0.f, px1 = 0.f, px2 = 0.f;       // phys point
    float dx0 = 0.f, dx1 = 0.f, dx2 = 0.f;       // data point
    if (active) {
        px0 = xp[3 * p]; px1 = xp[3 * p + 1]; px2 = xp[3 * p + 2];
        dx0 = xd[3 * p]; dx1 = xd[3 * p + 1]; dx2 = xd[3 * p + 2];
    }

    // ---- layer 0: 3 -> 64, own 8 neurons, all channels ----
    #pragma unroll 4
    for (int jj = 0; jj < 8; jj++) {
        int j = jbase + jj;
        float wx = __ldg(W0 + j);
        float wy = __ldg(W0 + HID + j);
        float wt = __ldg(W0 + 2 * HID + j);
        float bj = __ldg(b0 + j);
        float zh = bj + px0 * wx + px1 * wy + px2 * wt;
        float zd = bj + dx0 * wx + dx1 * wy + dx2 * wt;
        float t = my_tanhf(zh);
        float s = 1.f - t * t;
        P0[j * PTS + pt] = make_float2(t, s * wt);
        P1[j * PTS + pt] = make_float2(s * wx, s * wy);
        P2[j * PTS + pt] = make_float2(-2.f * t * s * (wx * wx + wy * wy),
                                       my_tanhf(zd));
    }

    float t_r[8];    // tanh(z) for own j, current layer (set in epi0)

    // ---- hidden layers 1..3 ----
    #pragma unroll 1
    for (int l = 0; l < 3; l++) {
        const float* W  = (l == 0) ? W1 : (l == 1) ? W2 : W3;
        const float* bb = (l == 0) ? b1 : (l == 1) ? b2 : b3;

        __syncthreads();   // FULL: prev-layer epi writes visible; wsh reads retired
        {
            const float4* src = (const float4*)W;
            float4*       dst = (float4*)wsh;
            #pragma unroll
            for (int k = 0; k < (HID * HID / 4) / BDP; k++)   // 2 float4/thread
                dst[k * BDP + tid] = src[k * BDP + tid];
        }
        __syncthreads();   // FULL: weights staged for both groups

        // --- pass0: (h, ut). zA = b + h@W ; zB = ut@W ---
        {
            unsigned long long zA[4], zB[4];
            #pragma unroll
            for (int m = 0; m < 4; m++) {
                float2 bv = __ldg((const float2*)bb + (jbase >> 1) + m);
                zA[m] = pack2(bv.x, bv.y);
                zB[m] = 0ull;
            }
            matvec2p(P0, wsh, zA, zB, pt, jbase);
            group_bar(grp);                 // group's reads of P0 done
            #pragma unroll
            for (int m = 0; m < 4; m++) {
                float2 zh = unpk(zA[m]);
                float2 zt = unpk(zB[m]);
                #pragma unroll
                for (int hh = 0; hh < 2; hh++) {
                    int j = jbase + 2 * m + hh;
                    float t = my_tanhf(hh ? zh.y : zh.x);
                    float s = 1.f - t * t;
                    t_r[2 * m + hh] = t;
                    P0[j * PTS + pt] = make_float2(t, s * (hh ? zt.y : zt.x));
                }
            }
        }

        // --- pass12: (ux, uy, L, hd) in one weight stream ---
        {
            unsigned long long zA[4], zB[4], zC[4], zD[4];
            #pragma unroll
            for (int m = 0; m < 4; m++) {
                float2 bv = __ldg((const float2*)bb + (jbase >> 1) + m);
                zA[m] = 0ull; zB[m] = 0ull; zC[m] = 0ull;
                zD[m] = pack2(bv.x, bv.y);  // data channel carries the bias
            }
            matvec4p(P1, P2, wsh, zA, zB, zC, zD, pt, jbase);
            group_bar(grp);                 // group's reads of P1/P2 done
            #pragma unroll
            for (int m = 0; m < 4; m++) {
                float2 zx = unpk(zA[m]);
                float2 zy = unpk(zB[m]);
                float2 zl = unpk(zC[m]);
                float2 zd = unpk(zD[m]);
                #pragma unroll
                for (int hh = 0; hh < 2; hh++) {
                    int j = jbase + 2 * m + hh;
                    float zxv = hh ? zx.y : zx.x;
                    float zyv = hh ? zy.y : zy.x;
                    float zlv = hh ? zl.y : zl.x;
                    float zdv = hh ? zd.y : zd.x;
                    float t = t_r[2 * m + hh];
                    float s = 1.f - t * t;
                    float q = zxv * zxv + zyv * zyv;   // epilogue-local
                    P1[j * PTS + pt] = make_float2(s * zxv, s * zyv);
                    P2[j * PTS + pt] = make_float2(s * zlv - 2.f * t * s * q,
                                                   my_tanhf(zdv));
                }
            }
        }
    }

    // ---- output layer: partials over own 8 neurons (all self-written) ----
    float at = 0.f, aL = 0.f, ad = 0.f;
    #pragma unroll 4
    for (int jj = 0; jj < 8; jj++) {
        int j = jbase + jj;
        float w = __ldg(W4 + j);
        at += P0[j * PTS + pt].y * w;
        float2 v2 = P2[j * PTS + pt];
        aL += v2.x * w;
        ad += v2.y * w;
    }
    float alpha = expf(__ldg(log_alpha));
    float rp = at - alpha * aL;             // partial residual (linear in partials)

    // FULL barrier: wsh (scratch alias) reads by BOTH groups must be retired
    __syncthreads();
    wsh[oct * PTS + pt]            = rp;
    wsh[8 * PTS + oct * PTS + pt]  = ad;
    group_bar(grp);                         // combine is pt-local -> group is enough

    double lr = 0.0, ld = 0.0;
    if (oct == 0 && active) {
        float r = rp, ah = ad;
        #pragma unroll
        for (int o = 1; o < 8; o++) {
            r  += wsh[o * PTS + pt];
            ah += wsh[8 * PTS + o * PTS + pt];
        }
        lr = (double)r * (double)r;
        ah += __ldg(b4);
        float d = ah - yd[p];
        ld = (double)d * (double)d;
    }

    // block reductions -> atomics (both sums)
    #pragma unroll
    for (int off = 16; off; off >>= 1) {
        lr += __shfl_down_sync(0xffffffffu, lr, off);
        ld += __shfl_down_sync(0xffffffffu, ld, off);
    }
    __syncthreads();
    double* red = (double*)sh;              // 2*NW doubles
    int lane = tid & 31, wid = tid >> 5;
    if (lane == 0) { red[wid] = lr; red[NW + wid] = ld; }
    __syncthreads();
    if (tid == 0) {
        double sr = 0.0, sd = 0.0;
        #pragma unroll
        for (int w = 0; w < NW; w++) { sr += red[w]; sd += red[NW + w]; }
        atomicAdd(&g_sums[1], sr);
        atomicAdd(&g_sums[0], sd);
    }
}

__global__ void k_final(const float* __restrict__ log_lambda,
                        const float* __restrict__ log_alpha,
                        float* __restrict__ out, int n)
{
    float data_loss = (float)(g_sums[0] / (double)n);
    float pde_loss  = (float)(g_sums[1] / (double)n);
    float alpha = expf(log_alpha[0]);
    float lam   = expf(log_lambda[0]);
    out[0] = data_loss + lam * pde_loss;
    out[1] = data_loss;
    out[2] = pde_loss;
    out[3] = alpha;
    out[4] = lam;
}

extern "C" void kernel_launch(void* const* d_in, const int* in_sizes, int n_in,
                              void* d_out, int out_size)
{
    const float* x_data     = (const float*)d_in[0];
    const float* y_data     = (const float*)d_in[1];
    const float* x_phys     = (const float*)d_in[2];
    const float* W0 = (const float*)d_in[3];  const float* b0 = (const float*)d_in[4];
    const float* W1 = (const float*)d_in[5];  const float* b1 = (const float*)d_in[6];
    const float* W2 = (const float*)d_in[7];  const float* b2 = (const float*)d_in[8];
    const float* W3 = (const float*)d_in[9];  const float* b3 = (const float*)d_in[10];
    const float* W4 = (const float*)d_in[11]; const float* b4 = (const float*)d_in[12];
    const float* log_lambda = (const float*)d_in[13];
    const float* log_alpha  = (const float*)d_in[14];
    float* out = (float*)d_out;

    int n = in_sizes[0] / 3;

    // 3 pair-buffers (96 KB) + 64x64 weights (16 KB) = 112 KB -> 2 CTAs/SM
    const int SH = (6 * HID * PTS + HID * HID) * (int)sizeof(float);
    cudaFuncSetAttribute(k_fused, cudaFuncAttributeMaxDynamicSharedMemorySize, SH);

    int grid = (n + PTS - 1) / PTS;

    k_zero<<<1, 1>>>();
    k_fused<<<grid, BDP, SH>>>(x_data, y_data, x_phys, W0, b0, W1, b1, W2, b2,
                               W3, b3, W4, b4, log_alpha, n);
    k_final<<<1, 1>>>(log_lambda, log_alpha, out, n);
}